// round 7
// baseline (speedup 1.0000x reference)
#include <cuda_runtime.h>
#include <cstdint>

// Integrator: y[b,c,n] = cumsum over time axis. 32 rows, T = 2^20.
//
// R7: two-phase (sum -> lookback -> rescan) sized for L2 retention.
//   2048 blocks x 16K elements, 7 blocks/SM (87.5% occ), 2 waves.
//   Resident phase-B live set = 1036 x 64KB = 66MB << 126MB L2, so the
//   phase-B re-read hits L2. Phase A: evict-normal loads. Phase B: __ldcs
//   (last use) + __stcs stores (don't evict the input live set).
//   Lookback: <=63 predecessors, <=2/lane, one MLP round, fixed grouping.

#define THREADS 256
#define SEG 16384                      // elements per block
#define CHUNK 4096                     // elements per phase-B chunk (256*16)
#define NCHUNK (SEG / CHUNK)           // 4
#define F4_PER_SEG (SEG / 4)           // 4096
#define F4_PER_CHUNK (CHUNK / 4)       // 1024
#define T_LEN 1048576
#define SEGS_PER_ROW (T_LEN / SEG)     // 64 (power of two)
#define NSEG 2048                      // 32 rows * 64

// Spine: flag (hi 32) | float bits (lo 32).
__device__ unsigned long long g_spine[NSEG];

__global__ void integrator_init_kernel() {
    int i = blockIdx.x * blockDim.x + threadIdx.x;
    if (i < NSEG) g_spine[i] = 0ULL;
}

__device__ __forceinline__ void spine_publish(unsigned long long* p, float v) {
    unsigned long long w = (1ULL << 32) | (unsigned long long)__float_as_uint(v);
    asm volatile("st.global.relaxed.gpu.b64 [%0], %1;" :: "l"(p), "l"(w) : "memory");
}

__device__ __forceinline__ unsigned long long spine_poll(const unsigned long long* p) {
    unsigned long long v;
    asm volatile("ld.global.relaxed.gpu.b64 %0, [%1];" : "=l"(v) : "l"(p) : "memory");
    return v;
}

__global__ __launch_bounds__(THREADS, 7)
void integrator_scan_kernel(const float* __restrict__ x, float* __restrict__ y) {
    __shared__ float s_warp[8];      // per-warp totals
    __shared__ float s_woff[8];      // exclusive warp offsets within chunk
    __shared__ float s_ctot;         // chunk total
    __shared__ float s_excl;         // exclusive prefix of this segment

    const int bid = blockIdx.x;
    const int seg_in_row = bid & (SEGS_PER_ROW - 1);
    const long long base = (long long)bid * SEG;

    const int t = threadIdx.x;
    const int lane = t & 31;
    const int warp = t >> 5;

    const float4* xv = reinterpret_cast<const float4*>(x + base);
    float4* yv = reinterpret_cast<float4*>(y + base);

    // ===== Phase A: segment sum (evict-normal reads fill L2 for phase B) =====
    float s0 = 0.f, s1 = 0.f, s2 = 0.f, s3 = 0.f;
    #pragma unroll 4
    for (int c = 0; c < F4_PER_SEG / THREADS; c++) {   // 16 iters
        float4 v = xv[c * THREADS + t];
        s0 += v.x; s1 += v.y; s2 += v.z; s3 += v.w;
    }
    float tsum = (s0 + s1) + (s2 + s3);
    #pragma unroll
    for (int d = 16; d; d >>= 1)
        tsum += __shfl_xor_sync(0xffffffffu, tsum, d);
    if (lane == 0) s_warp[warp] = tsum;
    __syncthreads();

    if (warp == 0) {
        float w = (lane < 8) ? s_warp[lane] : 0.0f;
        #pragma unroll
        for (int d = 4; d; d >>= 1)
            w += __shfl_xor_sync(0xffffffffu, w, d);
        float blocktot = __shfl_sync(0xffffffffu, w, 0);

        if (lane == 0) spine_publish(&g_spine[bid], blocktot);

        // Lookback: <=63 predecessors, <=2 per lane, MLP-batched, fixed reduce.
        float excl = 0.0f;
        if (seg_in_row > 0) {
            const int rowbase = bid - seg_in_row;
            const int cnt = (seg_in_row > lane) ? ((seg_in_row - lane + 31) >> 5) : 0;
            float v2[2];
            unsigned pend = (cnt > 0) ? ((1u << cnt) - 1u) : 0u;
            while (pend) {
                unsigned long long w2[2];
                #pragma unroll
                for (int i = 0; i < 2; i++)
                    if (pend & (1u << i))
                        w2[i] = spine_poll(&g_spine[rowbase + lane + 32 * i]);
                #pragma unroll
                for (int i = 0; i < 2; i++)
                    if ((pend & (1u << i)) && (unsigned)(w2[i] >> 32)) {
                        v2[i] = __uint_as_float((unsigned)w2[i]);
                        pend &= ~(1u << i);
                    }
            }
            float lsum = 0.0f;
            #pragma unroll
            for (int i = 0; i < 2; i++)
                if (i < cnt) lsum += v2[i];
            #pragma unroll
            for (int d = 16; d; d >>= 1)
                lsum += __shfl_xor_sync(0xffffffffu, lsum, d);
            excl = lsum;
        }
        if (lane == 0) s_excl = excl;
    }
    __syncthreads();

    // ===== Phase B: rescan 4 chunks; re-reads hit L2 (loaded in phase A) =====
    float carry = s_excl;

    #pragma unroll
    for (int c = 0; c < NCHUNK; c++) {
        const int cb = c * F4_PER_CHUNK;

        float4 a0 = __ldcs(xv + cb + t * 4 + 0);   // last use -> evict-first
        float4 a1 = __ldcs(xv + cb + t * 4 + 1);
        float4 a2 = __ldcs(xv + cb + t * 4 + 2);
        float4 a3 = __ldcs(xv + cb + t * 4 + 3);

        // thread-local inclusive scan of 16
        a0.y += a0.x; a0.z += a0.y; a0.w += a0.z;
        a1.x += a0.w; a1.y += a1.x; a1.z += a1.y; a1.w += a1.z;
        a2.x += a1.w; a2.y += a2.x; a2.z += a2.y; a2.w += a2.z;
        a3.x += a2.w; a3.y += a3.x; a3.z += a3.y; a3.w += a3.z;
        const float tot = a3.w;

        // warp inclusive scan of per-thread totals
        float incl = tot;
        #pragma unroll
        for (int d = 1; d < 32; d <<= 1) {
            float n = __shfl_up_sync(0xffffffffu, incl, d);
            if (lane >= d) incl += n;
        }
        if (lane == 31) s_warp[warp] = incl;
        const float thr_excl = incl - tot;

        __syncthreads();

        if (warp == 0) {
            float w = (lane < 8) ? s_warp[lane] : 0.0f;
            float wincl = w;
            #pragma unroll
            for (int d = 1; d < 8; d <<= 1) {
                float n = __shfl_up_sync(0xffffffffu, wincl, d);
                if (lane >= d) wincl += n;
            }
            if (lane < 8) s_woff[lane] = wincl - w;
            if (lane == 7) s_ctot = wincl;
        }

        __syncthreads();

        const float off = carry + s_woff[warp] + thr_excl;

        a0.x += off; a0.y += off; a0.z += off; a0.w += off;
        a1.x += off; a1.y += off; a1.z += off; a1.w += off;
        a2.x += off; a2.y += off; a2.z += off; a2.w += off;
        a3.x += off; a3.y += off; a3.z += off; a3.w += off;
        __stcs(yv + cb + t * 4 + 0, a0);
        __stcs(yv + cb + t * 4 + 1, a1);
        __stcs(yv + cb + t * 4 + 2, a2);
        __stcs(yv + cb + t * 4 + 3, a3);

        carry += s_ctot;
    }
}

extern "C" void kernel_launch(void* const* d_in, const int* in_sizes, int n_in,
                              void* d_out, int out_size) {
    const float* x = (const float*)d_in[0];
    float* y = (float*)d_out;

    const int n = out_size;              // 33554432
    const int nseg = n / SEG;            // 2048

    integrator_init_kernel<<<4, 512>>>();
    integrator_scan_kernel<<<nseg, THREADS>>>(x, y);
}

// round 8
// speedup vs baseline: 1.0244x; 1.0244x over previous
#include <cuda_runtime.h>
#include <cstdint>

// Integrator: y[b,c,n] = cumsum over time axis. 32 rows, T = 2^20.
//
// R8: single-wave two-phase with REVERSE-ORDER phase B.
//   1024 blocks x 32K elements, 7 blocks/SM -> whole grid is one wave.
//   Phase A: per-chunk block sums (8 chunks of 4096), chunk-offset scan,
//   publish aggregate. Lookback: <=31 preds, 1/lane, 1 round, deterministic.
//   Phase B: chunks processed 7..0 (reverse) so the re-read touches the
//   most-recently-cached L2 lines first; __ldcs re-reads + __stcs stores.

#define THREADS 256
#define SEG 32768                      // elements per block
#define CHUNK 4096                     // elements per chunk
#define NCHUNK (SEG / CHUNK)           // 8
#define F4_PER_CHUNK (CHUNK / 4)       // 1024
#define T_LEN 1048576
#define SEGS_PER_ROW (T_LEN / SEG)     // 32 (power of two)
#define NSEG 1024                      // 32 rows * 32

// Spine: flag (hi 32) | float bits (lo 32).
__device__ unsigned long long g_spine[NSEG];

__global__ void integrator_init_kernel() {
    int i = threadIdx.x;
    #pragma unroll
    for (int k = 0; k < NSEG / 256; k++)
        g_spine[k * 256 + i] = 0ULL;
}

__device__ __forceinline__ void spine_publish(unsigned long long* p, float v) {
    unsigned long long w = (1ULL << 32) | (unsigned long long)__float_as_uint(v);
    asm volatile("st.global.relaxed.gpu.b64 [%0], %1;" :: "l"(p), "l"(w) : "memory");
}

__device__ __forceinline__ unsigned long long spine_poll(const unsigned long long* p) {
    unsigned long long v;
    asm volatile("ld.global.relaxed.gpu.b64 %0, [%1];" : "=l"(v) : "l"(p) : "memory");
    return v;
}

__global__ __launch_bounds__(THREADS, 7)
void integrator_scan_kernel(const float* __restrict__ x, float* __restrict__ y) {
    __shared__ float s_cw[NCHUNK * 8];   // (chunk, warp) sums
    __shared__ float s_choff[NCHUNK];    // exclusive chunk offsets within segment
    __shared__ float s_warp[8];          // phase-B per-warp totals
    __shared__ float s_woff[8];          // phase-B exclusive warp offsets
    __shared__ float s_excl;             // exclusive prefix of this segment

    const int bid = blockIdx.x;
    const int seg_in_row = bid & (SEGS_PER_ROW - 1);
    const long long base = (long long)bid * SEG;

    const int t = threadIdx.x;
    const int lane = t & 31;
    const int warp = t >> 5;

    const float4* xv = reinterpret_cast<const float4*>(x + base);
    float4* yv = reinterpret_cast<float4*>(y + base);

    // ===== Phase A: per-chunk sums (evict-normal reads fill L2) =====
    #pragma unroll
    for (int c = 0; c < NCHUNK; c++) {
        const int fb = c * F4_PER_CHUNK + t * 4;
        float4 a0 = xv[fb + 0];
        float4 a1 = xv[fb + 1];
        float4 a2 = xv[fb + 2];
        float4 a3 = xv[fb + 3];
        float s = ((a0.x + a0.y) + (a0.z + a0.w))
                + ((a1.x + a1.y) + (a1.z + a1.w))
                + ((a2.x + a2.y) + (a2.z + a2.w))
                + ((a3.x + a3.y) + (a3.z + a3.w));
        #pragma unroll
        for (int d = 16; d; d >>= 1)
            s += __shfl_xor_sync(0xffffffffu, s, d);
        if (lane == 0) s_cw[c * 8 + warp] = s;
    }
    __syncthreads();

    if (warp == 0) {
        // chunk totals: lane c (c<8) sums its 8 warp entries
        float ctot = 0.0f;
        if (lane < NCHUNK) {
            #pragma unroll
            for (int w = 0; w < 8; w++)
                ctot += s_cw[lane * 8 + w];
        }
        // inclusive scan over 8 chunk totals
        float incl = ctot;
        #pragma unroll
        for (int d = 1; d < 8; d <<= 1) {
            float n = __shfl_up_sync(0xffffffffu, incl, d);
            if (lane >= d) incl += n;
        }
        if (lane < NCHUNK) s_choff[lane] = incl - ctot;
        const float blocktot = __shfl_sync(0xffffffffu, incl, NCHUNK - 1);

        if (lane == 0) spine_publish(&g_spine[bid], blocktot);

        // Lookback: <=31 predecessors, exactly one per lane, fixed reduce.
        float excl = 0.0f;
        if (seg_in_row > 0) {
            float v = 0.0f;
            if (lane < seg_in_row) {
                const unsigned long long* p = &g_spine[bid - seg_in_row + lane];
                unsigned long long e;
                do { e = spine_poll(p); } while ((unsigned)(e >> 32) == 0u);
                v = __uint_as_float((unsigned)e);
            }
            #pragma unroll
            for (int d = 16; d; d >>= 1)
                v += __shfl_xor_sync(0xffffffffu, v, d);
            excl = v;
        }
        if (lane == 0) s_excl = excl;
    }
    __syncthreads();

    // ===== Phase B: chunks in REVERSE order (best L2 temporal locality) =====
    const float seg_excl = s_excl;

    #pragma unroll
    for (int ci = NCHUNK - 1; ci >= 0; ci--) {
        const int cb = ci * F4_PER_CHUNK;
        const int fb = cb + t * 4;

        float4 a0 = __ldcs(xv + fb + 0);   // last use -> evict-first
        float4 a1 = __ldcs(xv + fb + 1);
        float4 a2 = __ldcs(xv + fb + 2);
        float4 a3 = __ldcs(xv + fb + 3);

        // thread-local inclusive scan of 16
        a0.y += a0.x; a0.z += a0.y; a0.w += a0.z;
        a1.x += a0.w; a1.y += a1.x; a1.z += a1.y; a1.w += a1.z;
        a2.x += a1.w; a2.y += a2.x; a2.z += a2.y; a2.w += a2.z;
        a3.x += a2.w; a3.y += a3.x; a3.z += a3.y; a3.w += a3.z;
        const float tot = a3.w;

        // warp inclusive scan of per-thread totals
        float incl = tot;
        #pragma unroll
        for (int d = 1; d < 32; d <<= 1) {
            float n = __shfl_up_sync(0xffffffffu, incl, d);
            if (lane >= d) incl += n;
        }
        if (lane == 31) s_warp[warp] = incl;
        const float thr_excl = incl - tot;

        __syncthreads();

        if (warp == 0) {
            float w = (lane < 8) ? s_warp[lane] : 0.0f;
            float wincl = w;
            #pragma unroll
            for (int d = 1; d < 8; d <<= 1) {
                float n = __shfl_up_sync(0xffffffffu, wincl, d);
                if (lane >= d) wincl += n;
            }
            if (lane < 8) s_woff[lane] = wincl - w;
        }

        __syncthreads();

        const float off = seg_excl + s_choff[ci] + s_woff[warp] + thr_excl;

        a0.x += off; a0.y += off; a0.z += off; a0.w += off;
        a1.x += off; a1.y += off; a1.z += off; a1.w += off;
        a2.x += off; a2.y += off; a2.z += off; a2.w += off;
        a3.x += off; a3.y += off; a3.z += off; a3.w += off;
        __stcs(yv + fb + 0, a0);
        __stcs(yv + fb + 1, a1);
        __stcs(yv + fb + 2, a2);
        __stcs(yv + fb + 3, a3);
    }
}

extern "C" void kernel_launch(void* const* d_in, const int* in_sizes, int n_in,
                              void* d_out, int out_size) {
    const float* x = (const float*)d_in[0];
    float* y = (float*)d_out;

    const int n = out_size;              // 33554432
    const int nseg = n / SEG;            // 1024

    integrator_init_kernel<<<1, 256>>>();
    integrator_scan_kernel<<<nseg, THREADS>>>(x, y);
}

// round 10
// speedup vs baseline: 1.2284x; 1.1992x over previous
#include <cuda_runtime.h>
#include <cstdint>

// Integrator: y[b,c,n] = cumsum over time axis. 32 rows, T = 2^20.
//
// R10: single-read register-resident scan (R9 concept, coverage bug fixed).
//   4096 blocks x 8192 elements. Each thread holds 8 float4 = 32 elements in
//   registers for the whole kernel (exact: 256 thr * 32 = 8192 = SEG).
//   Phase A: 8 independent streaming loads, serial-carry warp scans (lex[j]
//   includes warp-internal prefix), one 8-wide warp-0 scan. 2 barriers total.
//   Lookback: <=127 preds, <=4/lane, one MLP round, fixed grouping (determ.).
//   Phase B: add offsets + STG.128 only - no loads, no shfls, no barriers.
//   DRAM traffic = 256 MB (floor); no L2 reuse needed.

#define THREADS 256
#define WARPS 8
#define VPT 8                          // float4 per thread
#define SEG (THREADS * VPT * 4)        // 8192
#define F4_PER_WARP 256                // WSPAN/4 = 1024/4
#define T_LEN 1048576
#define SEGS_PER_ROW (T_LEN / SEG)     // 128 (power of two)
#define NSEG 4096                      // 32 rows * 128

// Spine: flag (hi 32) | float bits (lo 32).
__device__ unsigned long long g_spine[NSEG];

__global__ void integrator_init_kernel() {
    int i = blockIdx.x * blockDim.x + threadIdx.x;
    if (i < NSEG) g_spine[i] = 0ULL;
}

__device__ __forceinline__ void spine_publish(unsigned long long* p, float v) {
    unsigned long long w = (1ULL << 32) | (unsigned long long)__float_as_uint(v);
    asm volatile("st.global.relaxed.gpu.b64 [%0], %1;" :: "l"(p), "l"(w) : "memory");
}

__device__ __forceinline__ unsigned long long spine_poll(const unsigned long long* p) {
    unsigned long long v;
    asm volatile("ld.global.relaxed.gpu.b64 %0, [%1];" : "=l"(v) : "l"(p) : "memory");
    return v;
}

__global__ __launch_bounds__(THREADS)
void integrator_scan_kernel(const float* __restrict__ x, float* __restrict__ y) {
    __shared__ float s_warp[WARPS];   // per-warp totals
    __shared__ float s_woff[WARPS];   // exclusive warp offsets within segment
    __shared__ float s_excl;          // exclusive prefix of this segment

    const int bid = blockIdx.x;
    const int seg_in_row = bid & (SEGS_PER_ROW - 1);
    const long long base = (long long)bid * SEG;

    const int t = threadIdx.x;
    const int lane = t & 31;
    const int warp = t >> 5;

    const float4* xv = reinterpret_cast<const float4*>(x + base);
    float4* yv = reinterpret_cast<float4*>(y + base);

    // ===== Phase A: one streaming read, data stays in registers =====
    // Warp w owns float4 indices [w*256, (w+1)*256); sub-chunk j is
    // w*256 + j*32 + lane  ->  j*32+lane sweeps 0..255 (full coverage).
    float4 d[VPT];
    float lex[VPT];   // exclusive prefix of this lane's 4 elems within the warp span

    #pragma unroll
    for (int j = 0; j < VPT; j++)
        d[j] = __ldcs(xv + warp * F4_PER_WARP + j * 32 + lane);

    float carry = 0.0f;   // warp-internal running prefix across sub-chunks
    #pragma unroll
    for (int j = 0; j < VPT; j++) {
        const float s = (d[j].x + d[j].y) + (d[j].z + d[j].w);
        float incl = s;
        #pragma unroll
        for (int dd = 1; dd < 32; dd <<= 1) {
            float n = __shfl_up_sync(0xffffffffu, incl, dd);
            if (lane >= dd) incl += n;
        }
        lex[j] = carry + (incl - s);
        carry += __shfl_sync(0xffffffffu, incl, 31);
    }
    if (lane == 0) s_warp[warp] = carry;

    __syncthreads();

    if (warp == 0) {
        // scan the 8 warp totals
        const float v = (lane < WARPS) ? s_warp[lane] : 0.0f;
        float incl = v;
        #pragma unroll
        for (int dd = 1; dd < 8; dd <<= 1) {
            float n = __shfl_up_sync(0xffffffffu, incl, dd);
            if (lane >= dd) incl += n;
        }
        if (lane < WARPS) s_woff[lane] = incl - v;
        const float blocktot = __shfl_sync(0xffffffffu, incl, WARPS - 1);

        if (lane == 0) spine_publish(&g_spine[bid], blocktot);

        // Deterministic lookback: <=127 preds, <=4/lane, MLP-batched polling,
        // fixed grouping -> bitwise deterministic.
        float excl = 0.0f;
        if (seg_in_row > 0) {
            const int rowbase = bid - seg_in_row;
            const int cnt = (seg_in_row > lane) ? ((seg_in_row - lane + 31) >> 5) : 0;
            float v4[4];
            unsigned pend = (cnt > 0) ? ((1u << cnt) - 1u) : 0u;
            while (pend) {
                unsigned long long w4[4];
                #pragma unroll
                for (int i = 0; i < 4; i++)
                    if (pend & (1u << i))
                        w4[i] = spine_poll(&g_spine[rowbase + lane + 32 * i]);
                #pragma unroll
                for (int i = 0; i < 4; i++)
                    if ((pend & (1u << i)) && (unsigned)(w4[i] >> 32)) {
                        v4[i] = __uint_as_float((unsigned)w4[i]);
                        pend &= ~(1u << i);
                    }
            }
            float lsum = 0.0f;
            #pragma unroll
            for (int i = 0; i < 4; i++)
                if (i < cnt) lsum += v4[i];
            #pragma unroll
            for (int dd = 16; dd; dd >>= 1)
                lsum += __shfl_xor_sync(0xffffffffu, lsum, dd);
            excl = lsum;
        }
        if (lane == 0) s_excl = excl;
    }

    __syncthreads();

    // ===== Phase B: registers -> global. No loads, no shfls, no barriers. =====
    const float woff = s_excl + s_woff[warp];

    #pragma unroll
    for (int j = 0; j < VPT; j++) {
        const float off = woff + lex[j];
        const float r0 = off + d[j].x;
        const float r1 = r0 + d[j].y;
        const float r2 = r1 + d[j].z;
        const float r3 = r2 + d[j].w;
        __stcs(yv + warp * F4_PER_WARP + j * 32 + lane, make_float4(r0, r1, r2, r3));
    }
}

extern "C" void kernel_launch(void* const* d_in, const int* in_sizes, int n_in,
                              void* d_out, int out_size) {
    const float* x = (const float*)d_in[0];
    float* y = (float*)d_out;

    const int n = out_size;              // 33554432
    const int nseg = n / SEG;            // 4096

    integrator_init_kernel<<<16, 256>>>();
    integrator_scan_kernel<<<nseg, THREADS>>>(x, y);
}